// round 4
// baseline (speedup 1.0000x reference)
#include <cuda_runtime.h>

// Problem constants (fixed dataset):
//   x      [2, 200000, 32]  fp32
//   pos    [2, 200000, 3]   fp32  (uniform [0,1))
//   kernel [3,3,3,32,32]    fp32  (o-major: [o][ci][co], o = oi*9+oj*3+ok)
//   bias   [32]             fp32
//   out    [2, 32, 66,66,66] fp32
#define NPART   400000      // B*N
#define NPERB   200000      // N
#define DD      66
#define HWP     4356        // 66*66
#define DHW     287496      // 66*66*66
#define PT      32          // particles per warp tile
#define NTILES  12500       // NPART / PT  (== grid*NW exactly)
#define NW      4           // warps per block

// Channel-last scratch grid [2*DHW][32] for coalesced v4 atomics.
// Zero at module load; re-zeroed at the END of each launch for the next call.
__device__ float g_scratch[(size_t)2 * DHW * 32];   // 73.6 MB

// ---------------------------------------------------------------------------
__global__ void zero_scratch_kernel() {
    const size_t n4 = (size_t)2 * DHW * 32 / 4;
    float4* p = reinterpret_cast<float4*>(g_scratch);
    for (size_t i = (size_t)blockIdx.x * blockDim.x + threadIdx.x;
         i < n4; i += (size_t)gridDim.x * blockDim.x) {
        p[i] = make_float4(0.f, 0.f, 0.f, 0.f);
    }
}

// ---------------------------------------------------------------------------
// Scatter kernel (R4):
//  * __launch_bounds__(128,4): cap regs at 128 -> 16 warps/SM (was 153 -> 12).
//  * K for each (oi,oj) group staged ONCE per block into smem, pre-paired as
//    f32x2 (K2s), then warps fill their kk registers with conflict-free
//    LDS.64 instead of 96 scattered LDGs per warp per group.
//  * vbuf parity double-buffered -> single __syncwarp per 4-particle batch.
// ---------------------------------------------------------------------------
__global__ __launch_bounds__(NW * 32, 4) void scatter_kernel(
    const float* __restrict__ x,
    const float* __restrict__ pos,
    const float* __restrict__ kern,
    const float* __restrict__ bias)
{
    __shared__ __align__(16) float xs[NW][PT][36];      // 18432 B
    __shared__ float ws[NW][PT][9];                     //  4608 B
    __shared__ int   nb[NW][PT];                        //   512 B
    __shared__ __align__(16) float vbuf[NW][2][384];    // 12288 B
    __shared__ __align__(16) unsigned long long K2s[3][16][32]; // 12288 B

    const int tid  = threadIdx.x;
    const int w    = tid >> 5;
    const int lane = tid & 31;
    const int tile = blockIdx.x * NW + w;               // always < NTILES
    const int p0   = tile * PT;

    // Epilogue mapping (loop-invariant): r-th RED, lane covers float4
    // f = r*32+lane of the 96-float4 batch -> particle jj=f/24, off=(f%24)*4.
    int jj_r[3], q4_r[3];
#pragma unroll
    for (int r = 0; r < 3; ++r) {
        const int f = r * 32 + lane;
        jj_r[r] = f / 24;
        q4_r[r] = (f % 24) * 4;
    }

    // ---- stage particles: one per lane ----
    {
        const int j   = lane;
        const int pid = p0 + j;
        const float4* xp = reinterpret_cast<const float4*>(x + (size_t)pid * 32);
        float4* xd = reinterpret_cast<float4*>(&xs[w][j][0]);
#pragma unroll
        for (int t = 0; t < 8; ++t) xd[t] = xp[t];

        const float px = pos[pid * 3 + 0] * 64.f;
        const float py = pos[pid * 3 + 1] * 64.f;
        const float pz = pos[pid * 3 + 2] * 64.f;
        const int bx = (int)px, by = (int)py, bz = (int)pz;
        const float fx = px - (float)bx - 0.5f;
        const float fy = py - (float)by - 0.5f;
        const float fz = pz - (float)bz - 0.5f;
        ws[w][j][0] = 0.5f * (0.5f - fx) * (0.5f - fx);
        ws[w][j][1] = 0.75f - fx * fx;
        ws[w][j][2] = 0.5f * (0.5f + fx) * (0.5f + fx);
        ws[w][j][3] = 0.5f * (0.5f - fy) * (0.5f - fy);
        ws[w][j][4] = 0.75f - fy * fy;
        ws[w][j][5] = 0.5f * (0.5f + fy) * (0.5f + fy);
        ws[w][j][6] = 0.5f * (0.5f - fz) * (0.5f - fz);
        ws[w][j][7] = 0.75f - fz * fz;
        ws[w][j][8] = 0.5f * (0.5f + fz) * (0.5f + fz);
        const int b = (pid >= NPERB) ? 1 : 0;
        nb[w][j] = b * DHW + bx * HWP + by * DD + bz;
    }
    __syncwarp();

    const float bc = bias[lane];

    for (int oij = 0; oij < 9; ++oij) {
        const int oi = oij / 3, oj = oij % 3;

        // ---- cooperative K staging: pre-paired f32x2 into K2s ----
        __syncthreads();            // previous group's kk reads complete
#pragma unroll
        for (int s = 0; s < 12; ++s) {          // 12 * 128 = 1536 entries
            const int i  = s * 128 + tid;
            const int ok = i >> 9;              // /512
            const int rm = i & 511;
            const int t  = rm >> 5;
            const int c  = rm & 31;
            const float* kb = kern + (size_t)(oij * 3 + ok) * 1024 + t * 64 + c;
            const float a = kb[0];
            const float b2 = kb[32];
            unsigned long long pk;
            asm("mov.b64 %0, {%1, %2};" : "=l"(pk) : "f"(a), "f"(b2));
            K2s[ok][t][c] = pk;
        }
        __syncthreads();

        // ---- per-warp kk registers from smem (conflict-free LDS.64) ----
        unsigned long long kk[3][16];
#pragma unroll
        for (int ok = 0; ok < 3; ++ok)
#pragma unroll
            for (int t = 0; t < 16; ++t)
                kk[ok][t] = K2s[ok][t][lane];

        const int obase = oi * HWP + oj * DD;

        for (int j4 = 0; j4 < PT; j4 += 4) {
            float* const vb = &vbuf[w][(j4 >> 2) & 1][0];
#pragma unroll
            for (int u = 0; u < 4; ++u) {
                const int j = j4 + u;
                const ulonglong2* xq =
                    reinterpret_cast<const ulonglong2*>(&xs[w][j][0]);
                unsigned long long y0 = 0ull, y1 = 0ull, y2 = 0ull;
#pragma unroll
                for (int t = 0; t < 8; ++t) {
                    const ulonglong2 xv = xq[t];            // LDS.128 broadcast
                    asm("fma.rn.f32x2 %0, %1, %2, %0;" : "+l"(y0) : "l"(xv.x), "l"(kk[0][2 * t]));
                    asm("fma.rn.f32x2 %0, %1, %2, %0;" : "+l"(y0) : "l"(xv.y), "l"(kk[0][2 * t + 1]));
                    asm("fma.rn.f32x2 %0, %1, %2, %0;" : "+l"(y1) : "l"(xv.x), "l"(kk[1][2 * t]));
                    asm("fma.rn.f32x2 %0, %1, %2, %0;" : "+l"(y1) : "l"(xv.y), "l"(kk[1][2 * t + 1]));
                    asm("fma.rn.f32x2 %0, %1, %2, %0;" : "+l"(y2) : "l"(xv.x), "l"(kk[2][2 * t]));
                    asm("fma.rn.f32x2 %0, %1, %2, %0;" : "+l"(y2) : "l"(xv.y), "l"(kk[2][2 * t + 1]));
                }
                const float wij = ws[w][j][oi] * ws[w][j][3 + oj];
                float lo, hi;
                float* vu = vb + u * 96;
                asm("mov.b64 {%0, %1}, %2;" : "=f"(lo), "=f"(hi) : "l"(y0));
                vu[lane]      = (wij * ws[w][j][6]) * (lo + hi + bc);
                asm("mov.b64 {%0, %1}, %2;" : "=f"(lo), "=f"(hi) : "l"(y1));
                vu[32 + lane] = (wij * ws[w][j][7]) * (lo + hi + bc);
                asm("mov.b64 {%0, %1}, %2;" : "=f"(lo), "=f"(hi) : "l"(y2));
                vu[64 + lane] = (wij * ws[w][j][8]) * (lo + hi + bc);
            }
            __syncwarp();
            // Three full-warp float4 REDs cover all 4 particles (384 floats).
#pragma unroll
            for (int r = 0; r < 3; ++r) {
                const int node = nb[w][j4 + jj_r[r]] + obase;
                const float4 v =
                    *reinterpret_cast<const float4*>(vb + (r * 32 + lane) * 4);
                atomicAdd(reinterpret_cast<float4*>(
                              g_scratch + (size_t)node * 32 + q4_r[r]), v);
            }
            // no trailing sync: parity double-buffer + next batch's syncwarp
        }
    }
}

// ---------------------------------------------------------------------------
// Transpose scratch [b][node][c] -> out [b][c][node].
// ---------------------------------------------------------------------------
__global__ void transpose_kernel(float* __restrict__ out) {
    __shared__ float t[32][33];
    const int nd0 = blockIdx.x * 32;
    const int b   = blockIdx.y;
    const int tx  = threadIdx.x;      // 32
    const int ty  = threadIdx.y;      // 8
#pragma unroll
    for (int k = 0; k < 4; ++k) {
        const int nd = nd0 + ty + k * 8;
        if (nd < DHW)
            t[ty + k * 8][tx] = g_scratch[((size_t)b * DHW + nd) * 32 + tx];
    }
    __syncthreads();
    const int nd = nd0 + tx;
    if (nd < DHW) {
#pragma unroll
        for (int k = 0; k < 4; ++k) {
            const int c = ty + k * 8;
            out[((size_t)b * 32 + c) * DHW + nd] = t[tx][c];
        }
    }
}

// ---------------------------------------------------------------------------
// Order: scatter (profiled first), transpose (consume), zero (prep next call).
// ---------------------------------------------------------------------------
extern "C" void kernel_launch(void* const* d_in, const int* in_sizes, int n_in,
                              void* d_out, int out_size)
{
    const float* x    = reinterpret_cast<const float*>(d_in[0]);
    const float* pos  = reinterpret_cast<const float*>(d_in[1]);
    const float* kern = reinterpret_cast<const float*>(d_in[2]);
    const float* bias = reinterpret_cast<const float*>(d_in[3]);
    float* out = reinterpret_cast<float*>(d_out);

    scatter_kernel<<<NTILES / NW, NW * 32>>>(x, pos, kern, bias);
    transpose_kernel<<<dim3((DHW + 31) / 32, 2), dim3(32, 8)>>>(out);
    zero_scratch_kernel<<<4096, 256>>>();
}